// round 6
// baseline (speedup 1.0000x reference)
#include <cuda_runtime.h>
#include <cuda_bf16.h>
#include <cstdint>

#define NWIN   2048
#define WIN    64
#define DIM    256
#define HEADS  8
#define HD     32
#define QKV_N  768
#define MROWS  (NWIN*WIN)  // 131072

__device__ float g_q[(size_t)NWIN*HEADS*WIN*HD];
__device__ float g_k[(size_t)NWIN*HEADS*WIN*HD];
__device__ float g_v[(size_t)NWIN*HEADS*WIN*HD];
__device__ float g_ao[(size_t)NWIN*WIN*DIM];          // tf32-rounded by attention
__device__ float g_bm[(size_t)256*HEADS*WIN*WIN];     // bias+mask tables (33.5MB)
__device__ float g_xt[(size_t)MROWS*DIM];             // tf32-rounded x
__device__ float g_wq[QKV_N*DIM];                     // tf32-rounded qkv_w
__device__ float g_wp[DIM*DIM];                       // tf32-rounded proj_w

__device__ __forceinline__ unsigned f2tf32(float f) {
    unsigned r;
    asm("cvt.rna.tf32.f32 %0, %1;" : "=r"(r) : "f"(f));
    return r;
}
__device__ __forceinline__ float f2tf32f(float f) { return __uint_as_float(f2tf32(f)); }
__device__ __forceinline__ unsigned fbits(float x) { return __float_as_uint(x); }

__device__ __forceinline__ void mma_tf32(float c[4],
                                         unsigned a0, unsigned a1, unsigned a2, unsigned a3,
                                         unsigned b0, unsigned b1) {
    asm volatile(
        "mma.sync.aligned.m16n8k8.row.col.f32.tf32.tf32.f32 "
        "{%0,%1,%2,%3}, {%4,%5,%6,%7}, {%8,%9}, {%0,%1,%2,%3};"
        : "+f"(c[0]), "+f"(c[1]), "+f"(c[2]), "+f"(c[3])
        : "r"(a0), "r"(a1), "r"(a2), "r"(a3), "r"(b0), "r"(b1));
}

__device__ __forceinline__ void cp16(uint32_t dst, const void* src) {
    asm volatile("cp.async.cg.shared.global [%0], [%1], 16;" :: "r"(dst), "l"(src));
}

// ---------------------------------------------------------------------------
// TF32 pre-rounding pass (vectorized)
// ---------------------------------------------------------------------------
__global__ void conv_tf32(const float* __restrict__ src, float* __restrict__ dst, int n4)
{
    const int i = blockIdx.x * 256 + threadIdx.x;
    if (i < n4) {
        float4 v = ((const float4*)src)[i];
        v.x = f2tf32f(v.x); v.y = f2tf32f(v.y); v.z = f2tf32f(v.z); v.w = f2tf32f(v.w);
        ((float4*)dst)[i] = v;
    }
}

// ---------------------------------------------------------------------------
// bias+mask tables: g_bm[((w*8)+h)*4096 + e] = bt[rpi[e]*8+h] + mask[w*4096+e]
// ---------------------------------------------------------------------------
__global__ void bm_pre(const float* __restrict__ bt, const int* __restrict__ rpi,
                       const float* __restrict__ mask)
{
    const int idx = blockIdx.x * 256 + threadIdx.x;
    const int e = idx & 4095;
    const int h = (idx >> 12) & 7;
    const int w = idx >> 15;
    g_bm[idx] = bt[rpi[e] * HEADS + h] + mask[w * 4096 + e];
}

// ---------------------------------------------------------------------------
// cp.async pipelined GEMM. Inputs pre-rounded to tf32. Block 128x128, 4 warps
// (warp 64x64), BK=32, 2-stage smem double buffer.
// ---------------------------------------------------------------------------
#define SA 36
#define GEMM_SMEM_FLOATS (4*4608)
#define GEMM_SMEM_BYTES  (GEMM_SMEM_FLOATS*4)

template<bool QKV>
__global__ void __launch_bounds__(128) mma_gemm(const float* __restrict__ A,
                                                const float* __restrict__ W,
                                                const float* __restrict__ bias,
                                                float* __restrict__ out)
{
    extern __shared__ float smg[];
    float* Asb[2] = { smg,        smg + 4608 };
    float* Bsb[2] = { smg + 9216, smg + 13824 };
    uint32_t sA[2], sB[2];
    #pragma unroll
    for (int s = 0; s < 2; s++) {
        sA[s] = (uint32_t)__cvta_generic_to_shared(Asb[s]);
        sB[s] = (uint32_t)__cvta_generic_to_shared(Bsb[s]);
    }

    const int rowBase = blockIdx.y * 128;
    const int colBase = blockIdx.x * 128;
    const int tid  = threadIdx.x;
    const int lane = tid & 31;
    const int warp = tid >> 5;
    const int warpM = warp >> 1, warpN = warp & 1;
    const int g  = lane >> 2, tg = lane & 3;
    const int m0 = warpM * 64, n0 = warpN * 64;

    const int lr0 = tid >> 3;            // + 16*i
    const int lc4 = (tid & 7) * 4;

    auto issue = [&](int buf, int kb) {
        #pragma unroll
        for (int i = 0; i < 8; i++) {
            const int r = lr0 + 16 * i;
            const uint32_t off = (uint32_t)(r * SA + lc4) * 4;
            cp16(sA[buf] + off, &A[(size_t)(rowBase + r) * DIM + kb + lc4]);
            cp16(sB[buf] + off, &W[(size_t)(colBase + r) * DIM + kb + lc4]);
        }
        asm volatile("cp.async.commit_group;");
    };

    issue(0, 0);
    issue(1, 32);

    float acc[4][8][4] = {};

    for (int it = 0; it < 8; it++) {
        if (it == 7) asm volatile("cp.async.wait_group 0;");
        else         asm volatile("cp.async.wait_group 1;");
        __syncthreads();
        const float* as = Asb[it & 1];
        const float* bs = Bsb[it & 1];

        #pragma unroll
        for (int ks = 0; ks < 4; ks++) {
            const int k0 = ks * 8;
            unsigned a[4][4];
            #pragma unroll
            for (int am = 0; am < 4; am++) {
                const int mr = m0 + am * 16;
                a[am][0] = fbits(as[(mr + g)     * SA + k0 + tg]);
                a[am][1] = fbits(as[(mr + g + 8) * SA + k0 + tg]);
                a[am][2] = fbits(as[(mr + g)     * SA + k0 + tg + 4]);
                a[am][3] = fbits(as[(mr + g + 8) * SA + k0 + tg + 4]);
            }
            unsigned bf[8][2];
            #pragma unroll
            for (int an = 0; an < 8; an++) {
                const int nr = n0 + an * 8;
                bf[an][0] = fbits(bs[(nr + g) * SA + k0 + tg]);
                bf[an][1] = fbits(bs[(nr + g) * SA + k0 + tg + 4]);
            }
            #pragma unroll
            for (int am = 0; am < 4; am++)
                #pragma unroll
                for (int an = 0; an < 8; an++)
                    mma_tf32(acc[am][an], a[am][0], a[am][1], a[am][2], a[am][3],
                             bf[an][0], bf[an][1]);
        }
        __syncthreads();
        if (it < 6) issue(it & 1, (it + 2) * 32);
    }

    #pragma unroll
    for (int am = 0; am < 4; am++) {
        #pragma unroll
        for (int an = 0; an < 8; an++) {
            const int col = colBase + n0 + an * 8 + 2 * tg;
            const float bi0 = bias[col], bi1 = bias[col + 1];
            #pragma unroll
            for (int half = 0; half < 2; half++) {
                const int row = rowBase + m0 + am * 16 + g + 8 * half;
                float2 v;
                v.x = acc[am][an][2 * half]     + bi0;
                v.y = acc[am][an][2 * half + 1] + bi1;
                if (QKV) {
                    const int b = row >> 6, n = row & 63;
                    const int which = col >> 8;
                    const int h = (col >> 5) & 7;
                    const int d = col & 31;
                    float* dst = (which == 0) ? g_q : (which == 1) ? g_k : g_v;
                    *(float2*)&dst[((((size_t)b * HEADS + h) * WIN) + n) * HD + d] = v;
                } else {
                    *(float2*)&out[(size_t)row * DIM + col] = v;
                }
            }
        }
    }
}

// ---------------------------------------------------------------------------
// Attention, 3xTF32 MMA, 256 threads (8 warps: 4 row-groups x 2 col-halves).
// ---------------------------------------------------------------------------
#define AP 36
#define VP 40
#define PP 68
#define SQH 0
#define SQL 2304
#define SKH 4608
#define SKL 6912
#define SVH 9216
#define SVL 11776
#define SAT 0        // alias over qh+ql: logits, then P-hi
#define SPL 4608     // alias over kh+kl: P-lo
#define ATTN_SMEM_FLOATS 14336
#define ATTN_SMEM_BYTES  (ATTN_SMEM_FLOATS * 4)

__global__ void __launch_bounds__(256) attn_kernel(const float* __restrict__ logit_scale)
{
    extern __shared__ float sm[];
    const int bh = blockIdx.x;
    const int b  = bh >> 3;
    const int h  = bh & 7;
    const int tid  = threadIdx.x;
    const int lane = tid & 31;
    const int warp = tid >> 5;       // 0..7
    const int g  = lane >> 2, tg = lane & 3;
    const int wm = warp >> 1, wn = warp & 1;
    const int m0 = wm * 16;
    const int r0 = m0 + g, r1 = r0 + 8;

    // Phase 0: load q,k,v (64x32 fp32 each)
    const size_t base = (size_t)bh * WIN * HD;
    #pragma unroll
    for (int i = 0; i < 2; i++) {
        const int idx = tid + 256 * i;          // 0..511
        const int n = idx >> 3, c = (idx & 7) * 4;
        *(float4*)&sm[SQH + n * AP + c] = *(const float4*)&g_q[base + n * HD + c];
        *(float4*)&sm[SKH + n * AP + c] = *(const float4*)&g_k[base + n * HD + c];
        *(float4*)&sm[SVH + n * VP + c] = *(const float4*)&g_v[base + n * HD + c];
    }
    __syncthreads();

    // Phase 1: tid<128 -> q/k row norm + hi/lo split; tid>=128 -> v hi/lo split
    if (tid < 128) {
        const float ls = __expf(fminf(logit_scale[h], 4.6051701859880914f));
        float* rowp = (tid < 64) ? &sm[SQH + tid * AP] : &sm[SKH + (tid - 64) * AP];
        float* lop  = (tid < 64) ? &sm[SQL + tid * AP] : &sm[SKL + (tid - 64) * AP];
        float s = 0.f;
        #pragma unroll
        for (int d = 0; d < HD; d++) s += rowp[d] * rowp[d];
        float inv = 1.0f / fmaxf(sqrtf(s), 1e-12f);
        if (tid < 64) inv *= ls;
        #pragma unroll
        for (int d = 0; d < HD; d++) {
            const float x = rowp[d] * inv;
            const float hf = f2tf32f(x);
            rowp[d] = hf;
            lop[d] = f2tf32f(x - hf);
        }
    } else {
        #pragma unroll
        for (int j = 0; j < 8; j++) {
            const int e = (tid - 128) * 8 + j;   // covers 0..1023 (x2 halves below)
            #pragma unroll
            for (int hhalf = 0; hhalf < 2; hhalf++) {
                const int ee = e + 1024 * hhalf;
                const int n = ee >> 5, d = ee & 31;
                const float x = sm[SVH + n * VP + d];
                const float hf = f2tf32f(x);
                sm[SVH + n * VP + d] = hf;
                sm[SVL + n * VP + d] = f2tf32f(x - hf);
            }
        }
    }
    __syncthreads();

    // Phase 2: QK^T 3xTF32. warp -> rows [m0,m0+16), cols [wn*32, +32).
    float acc[4][4] = {};
    #pragma unroll
    for (int ka = 0; ka < 4; ka++) {
        const int k0 = ka * 8;
        unsigned ah[4], al[4];
        ah[0] = fbits(sm[SQH + (m0 + g)     * AP + k0 + tg]);
        ah[1] = fbits(sm[SQH + (m0 + g + 8) * AP + k0 + tg]);
        ah[2] = fbits(sm[SQH + (m0 + g)     * AP + k0 + tg + 4]);
        ah[3] = fbits(sm[SQH + (m0 + g + 8) * AP + k0 + tg + 4]);
        al[0] = fbits(sm[SQL + (m0 + g)     * AP + k0 + tg]);
        al[1] = fbits(sm[SQL + (m0 + g + 8) * AP + k0 + tg]);
        al[2] = fbits(sm[SQL + (m0 + g)     * AP + k0 + tg + 4]);
        al[3] = fbits(sm[SQL + (m0 + g + 8) * AP + k0 + tg + 4]);
        #pragma unroll
        for (int an = 0; an < 4; an++) {
            const int nr = wn * 32 + an * 8;
            unsigned bh0 = fbits(sm[SKH + (nr + g) * AP + k0 + tg]);
            unsigned bh1 = fbits(sm[SKH + (nr + g) * AP + k0 + tg + 4]);
            unsigned bl0 = fbits(sm[SKL + (nr + g) * AP + k0 + tg]);
            unsigned bl1 = fbits(sm[SKL + (nr + g) * AP + k0 + tg + 4]);
            mma_tf32(acc[an], ah[0], ah[1], ah[2], ah[3], bh0, bh1);
            mma_tf32(acc[an], ah[0], ah[1], ah[2], ah[3], bl0, bl1);
            mma_tf32(acc[an], al[0], al[1], al[2], al[3], bh0, bh1);
        }
    }

    // Add bias+mask from L2-resident table (registers, no staging)
    {
        const float* bm = g_bm + ((size_t)((b & 255) * 8 + h) << 12);
        #pragma unroll
        for (int an = 0; an < 4; an++) {
            const int c = wn * 32 + an * 8 + 2 * tg;
            float2 b0 = *(const float2*)&bm[r0 * 64 + c];
            float2 b1 = *(const float2*)&bm[r1 * 64 + c];
            acc[an][0] += b0.x; acc[an][1] += b0.y;
            acc[an][2] += b1.x; acc[an][3] += b1.y;
        }
    }
    __syncthreads();   // all q/k smem reads done before SAT/SPL alias writes

    // Store raw logits to SAT (fp32)
    #pragma unroll
    for (int an = 0; an < 4; an++) {
        const int c = wn * 32 + an * 8 + 2 * tg;
        *(float2*)&sm[SAT + r0 * PP + c] = make_float2(acc[an][0], acc[an][1]);
        *(float2*)&sm[SAT + r1 * PP + c] = make_float2(acc[an][2], acc[an][3]);
    }
    __syncthreads();

    // Softmax: warp handles rows warp, warp+8, ... writes P hi (SAT) / lo (SPL)
    for (int i = warp; i < WIN; i += 8) {
        float a0 = sm[SAT + i * PP + lane], a1 = sm[SAT + i * PP + lane + 32];
        float m = fmaxf(a0, a1);
        #pragma unroll
        for (int o = 16; o; o >>= 1) m = fmaxf(m, __shfl_xor_sync(0xffffffffu, m, o));
        float e0 = __expf(a0 - m), e1 = __expf(a1 - m);
        float s = e0 + e1;
        #pragma unroll
        for (int o = 16; o; o >>= 1) s += __shfl_xor_sync(0xffffffffu, s, o);
        const float rinv = 1.0f / s;
        e0 *= rinv; e1 *= rinv;
        const float h0 = f2tf32f(e0), h1 = f2tf32f(e1);
        sm[SAT + i * PP + lane]      = h0;
        sm[SAT + i * PP + lane + 32] = h1;
        sm[SPL + i * PP + lane]      = f2tf32f(e0 - h0);
        sm[SPL + i * PP + lane + 32] = f2tf32f(e1 - h1);
    }
    __syncthreads();

    // Phase 5: out = P @ V, 3xTF32. warp -> rows [m0,+16), cols [wn*16,+16).
    float oacc[2][4] = {};
    #pragma unroll
    for (int kj = 0; kj < 8; kj++) {
        const int k0 = kj * 8;
        unsigned ah[4], al[4];
        ah[0] = fbits(sm[SAT + (m0 + g)     * PP + k0 + tg]);
        ah[1] = fbits(sm[SAT + (m0 + g + 8) * PP + k0 + tg]);
        ah[2] = fbits(sm[SAT + (m0 + g)     * PP + k0 + tg + 4]);
        ah[3] = fbits(sm[SAT + (m0 + g + 8) * PP + k0 + tg + 4]);
        al[0] = fbits(sm[SPL + (m0 + g)     * PP + k0 + tg]);
        al[1] = fbits(sm[SPL + (m0 + g + 8) * PP + k0 + tg]);
        al[2] = fbits(sm[SPL + (m0 + g)     * PP + k0 + tg + 4]);
        al[3] = fbits(sm[SPL + (m0 + g + 8) * PP + k0 + tg + 4]);
        #pragma unroll
        for (int dn = 0; dn < 2; dn++) {
            const int nn = wn * 16 + dn * 8;
            unsigned bh0 = fbits(sm[SVH + (k0 + tg)     * VP + nn + g]);
            unsigned bh1 = fbits(sm[SVH + (k0 + tg + 4) * VP + nn + g]);
            unsigned bl0 = fbits(sm[SVL + (k0 + tg)     * VP + nn + g]);
            unsigned bl1 = fbits(sm[SVL + (k0 + tg + 4) * VP + nn + g]);
            mma_tf32(oacc[dn], ah[0], ah[1], ah[2], ah[3], bh0, bh1);
            mma_tf32(oacc[dn], ah[0], ah[1], ah[2], ah[3], bl0, bl1);
            mma_tf32(oacc[dn], al[0], al[1], al[2], al[3], bh0, bh1);
        }
    }

    // Write ao pre-rounded to tf32 (proj GEMM consumes raw)
    float* aop = g_ao + (size_t)b * WIN * DIM + h * HD;
    #pragma unroll
    for (int dn = 0; dn < 2; dn++) {
        const int c = wn * 16 + dn * 8 + 2 * tg;
        float2 v0 = make_float2(f2tf32f(oacc[dn][0]), f2tf32f(oacc[dn][1]));
        float2 v1 = make_float2(f2tf32f(oacc[dn][2]), f2tf32f(oacc[dn][3]));
        *(float2*)&aop[(size_t)r0 * DIM + c] = v0;
        *(float2*)&aop[(size_t)r1 * DIM + c] = v1;
    }
}

// ---------------------------------------------------------------------------
extern "C" void kernel_launch(void* const* d_in, const int* in_sizes, int n_in,
                              void* d_out, int out_size)
{
    const float* x        = (const float*)d_in[0];
    const float* mask     = (const float*)d_in[1];
    const float* qkv_w    = (const float*)d_in[2];
    const float* qkv_b    = (const float*)d_in[3];
    const float* proj_w   = (const float*)d_in[4];
    const float* proj_b   = (const float*)d_in[5];
    const float* lscale   = (const float*)d_in[6];
    const float* btable   = (const float*)d_in[7];
    const int*   rpi      = (const int*)d_in[8];
    float* out = (float*)d_out;

    cudaFuncSetAttribute(attn_kernel, cudaFuncAttributeMaxDynamicSharedMemorySize,
                         ATTN_SMEM_BYTES);
    cudaFuncSetAttribute(mma_gemm<true>, cudaFuncAttributeMaxDynamicSharedMemorySize,
                         GEMM_SMEM_BYTES);
    cudaFuncSetAttribute(mma_gemm<false>, cudaFuncAttributeMaxDynamicSharedMemorySize,
                         GEMM_SMEM_BYTES);

    float *xt, *wq, *wp, *ao;
    cudaGetSymbolAddress((void**)&xt, g_xt);
    cudaGetSymbolAddress((void**)&wq, g_wq);
    cudaGetSymbolAddress((void**)&wp, g_wp);
    cudaGetSymbolAddress((void**)&ao, g_ao);

    // 0) TF32 pre-rounding + bias/mask tables
    conv_tf32<<<(MROWS*DIM/4 + 255)/256, 256>>>(x, xt, MROWS*DIM/4);
    conv_tf32<<<(QKV_N*DIM/4 + 255)/256, 256>>>(qkv_w, wq, QKV_N*DIM/4);
    conv_tf32<<<(DIM*DIM/4 + 255)/256, 256>>>(proj_w, wp, DIM*DIM/4);
    bm_pre<<<32768, 256>>>(btable, rpi, mask);

    // 1) QKV projection
    {
        dim3 grid(QKV_N / 128, MROWS / 128);
        mma_gemm<true><<<grid, 128, GEMM_SMEM_BYTES>>>(xt, wq, qkv_b, nullptr);
    }
    // 2) Attention per (window, head)
    {
        attn_kernel<<<NWIN * HEADS, 256, ATTN_SMEM_BYTES>>>(lscale);
    }
    // 3) Output projection
    {
        dim3 grid(DIM / 128, MROWS / 128);
        mma_gemm<false><<<grid, 128, GEMM_SMEM_BYTES>>>(ao, wp, proj_b, out);
    }
}

// round 7
// speedup vs baseline: 1.1291x; 1.1291x over previous
#include <cuda_runtime.h>
#include <cuda_bf16.h>
#include <cstdint>

#define NWIN   2048
#define WIN    64
#define DIM    256
#define HEADS  8
#define HD     32
#define QKV_N  768
#define MROWS  (NWIN*WIN)  // 131072

__device__ float g_q[(size_t)NWIN*HEADS*WIN*HD];
__device__ float g_k[(size_t)NWIN*HEADS*WIN*HD];
__device__ float g_v[(size_t)NWIN*HEADS*WIN*HD];
__device__ float g_ao[(size_t)NWIN*WIN*DIM];
__device__ float g_bm[(size_t)256*HEADS*WIN*WIN];  // bias+mask tables (33.5MB)

__device__ __forceinline__ unsigned f2tf32(float f) {
    unsigned r;
    asm("cvt.rna.tf32.f32 %0, %1;" : "=r"(r) : "f"(f));
    return r;
}
__device__ __forceinline__ unsigned fbits(float x) { return __float_as_uint(x); }

__device__ __forceinline__ void mma_tf32(float c[4],
                                         unsigned a0, unsigned a1, unsigned a2, unsigned a3,
                                         unsigned b0, unsigned b1) {
    asm volatile(
        "mma.sync.aligned.m16n8k8.row.col.f32.tf32.tf32.f32 "
        "{%0,%1,%2,%3}, {%4,%5,%6,%7}, {%8,%9}, {%0,%1,%2,%3};"
        : "+f"(c[0]), "+f"(c[1]), "+f"(c[2]), "+f"(c[3])
        : "r"(a0), "r"(a1), "r"(a2), "r"(a3), "r"(b0), "r"(b1));
}

__device__ __forceinline__ void mma_bf16(float c[4],
                                         unsigned a0, unsigned a1, unsigned a2, unsigned a3,
                                         unsigned b0, unsigned b1) {
    asm volatile(
        "mma.sync.aligned.m16n8k16.row.col.f32.bf16.bf16.f32 "
        "{%0,%1,%2,%3}, {%4,%5,%6,%7}, {%8,%9}, {%0,%1,%2,%3};"
        : "+f"(c[0]), "+f"(c[1]), "+f"(c[2]), "+f"(c[3])
        : "r"(a0), "r"(a1), "r"(a2), "r"(a3), "r"(b0), "r"(b1));
}

__device__ __forceinline__ uint32_t pack_bf16(float a, float b) {
    __nv_bfloat162 t = __floats2bfloat162_rn(a, b);
    return *(uint32_t*)&t;
}
__device__ __forceinline__ float bf16hi(float x) {
    return __bfloat162float(__float2bfloat16_rn(x));
}

// ---------------------------------------------------------------------------
// GEMM (round-3 proven): C = A @ W^T + bias, K=256. Block 128x128, 4 warps,
// warp 64x64, BK=32, single buffer.
// ---------------------------------------------------------------------------
#define SA 36

template<bool QKV>
__global__ void __launch_bounds__(128, 2) mma_gemm(const float* __restrict__ A,
                                                   const float* __restrict__ W,
                                                   const float* __restrict__ bias,
                                                   float* __restrict__ out)
{
    const int K = DIM;
    __shared__ unsigned As[128 * SA];
    __shared__ unsigned Bs[128 * SA];

    const int rowBase = blockIdx.y * 128;
    const int colBase = blockIdx.x * 128;
    const int tid  = threadIdx.x;
    const int lane = tid & 31;
    const int warp = tid >> 5;
    const int warpM = warp >> 1;
    const int warpN = warp & 1;
    const int g  = lane >> 2;
    const int tg = lane & 3;
    const int m0 = warpM * 64;
    const int n0 = warpN * 64;

    float acc[4][8][4] = {};

    for (int kb = 0; kb < K; kb += 32) {
        #pragma unroll
        for (int i = 0; i < 8; i++) {
            const int idx = tid + 128 * i;
            const int r = idx >> 3, c4 = idx & 7;
            float4 v = *(const float4*)&A[(size_t)(rowBase + r) * K + kb + c4 * 4];
            uint4 u = make_uint4(f2tf32(v.x), f2tf32(v.y), f2tf32(v.z), f2tf32(v.w));
            *(uint4*)&As[r * SA + c4 * 4] = u;
            float4 w = *(const float4*)&W[(size_t)(colBase + r) * K + kb + c4 * 4];
            uint4 uw = make_uint4(f2tf32(w.x), f2tf32(w.y), f2tf32(w.z), f2tf32(w.w));
            *(uint4*)&Bs[r * SA + c4 * 4] = uw;
        }
        __syncthreads();

        #pragma unroll
        for (int ks = 0; ks < 4; ks++) {
            const int k0 = ks * 8;
            unsigned a[4][4];
            #pragma unroll
            for (int am = 0; am < 4; am++) {
                const int mr = m0 + am * 16;
                a[am][0] = As[(mr + g)     * SA + k0 + tg];
                a[am][1] = As[(mr + g + 8) * SA + k0 + tg];
                a[am][2] = As[(mr + g)     * SA + k0 + tg + 4];
                a[am][3] = As[(mr + g + 8) * SA + k0 + tg + 4];
            }
            unsigned bf[8][2];
            #pragma unroll
            for (int an = 0; an < 8; an++) {
                const int nr = n0 + an * 8;
                bf[an][0] = Bs[(nr + g) * SA + k0 + tg];
                bf[an][1] = Bs[(nr + g) * SA + k0 + tg + 4];
            }
            #pragma unroll
            for (int am = 0; am < 4; am++)
                #pragma unroll
                for (int an = 0; an < 8; an++)
                    mma_tf32(acc[am][an], a[am][0], a[am][1], a[am][2], a[am][3],
                             bf[an][0], bf[an][1]);
        }
        __syncthreads();
    }

    #pragma unroll
    for (int am = 0; am < 4; am++) {
        #pragma unroll
        for (int an = 0; an < 8; an++) {
            const int col = colBase + n0 + an * 8 + 2 * tg;
            const float bi0 = bias[col], bi1 = bias[col + 1];
            #pragma unroll
            for (int half = 0; half < 2; half++) {
                const int row = rowBase + m0 + am * 16 + g + 8 * half;
                float2 v;
                v.x = acc[am][an][2 * half]     + bi0;
                v.y = acc[am][an][2 * half + 1] + bi1;
                if (QKV) {
                    const int b = row >> 6, n = row & 63;
                    const int which = col >> 8;
                    const int h = (col >> 5) & 7;
                    const int d = col & 31;
                    float* dst = (which == 0) ? g_q : (which == 1) ? g_k : g_v;
                    *(float2*)&dst[((((size_t)b * HEADS + h) * WIN) + n) * HD + d] = v;
                } else {
                    *(float2*)&out[(size_t)row * DIM + col] = v;
                }
            }
        }
    }
}

// ---------------------------------------------------------------------------
// bias+mask tables
// ---------------------------------------------------------------------------
__global__ void bm_pre(const float* __restrict__ bt, const int* __restrict__ rpi,
                       const float* __restrict__ mask)
{
    const int idx = blockIdx.x * 256 + threadIdx.x;
    const int e = idx & 4095;
    const int h = (idx >> 12) & 7;
    const int w = idx >> 15;
    g_bm[idx] = bt[rpi[e] * HEADS + h] + mask[w * 4096 + e];
}

// ---------------------------------------------------------------------------
// Attention, 3-term bf16 MMA. One block per (window,head), 128 threads.
// smem (bytes):
//  [0,18432)      fp32 qs[64*36], ks[64*36]  -> later logits at[64*68] fp32
//  [18432,38912)  bf16 qhi/qlo/khi/klo (pitch 40) -> later P hi/lo (pitch 72)
//  [38912,48128)  bf16 vt hi/lo (32 x pitch 72), V transposed [d][n]
// ---------------------------------------------------------------------------
#define QP  40   // bf16 pitch for q/k
#define ATP 68   // fp32 pitch for logits
#define PPB 72   // bf16 pitch for P
#define VTP 72   // bf16 pitch for vt
#define ATTN_SMEM_BYTES 48128

__global__ void __launch_bounds__(128) attn_kernel(const float* __restrict__ logit_scale)
{
    extern __shared__ char smb[];
    float* qs  = (float*)(smb);
    float* ksf = (float*)(smb + 9216);
    float* at  = (float*)(smb);                      // alias (after norm phase)
    __nv_bfloat16* qhi = (__nv_bfloat16*)(smb + 18432);
    __nv_bfloat16* qlo = (__nv_bfloat16*)(smb + 23552);
    __nv_bfloat16* khi = (__nv_bfloat16*)(smb + 28672);
    __nv_bfloat16* klo = (__nv_bfloat16*)(smb + 33792);
    __nv_bfloat16* phi = (__nv_bfloat16*)(smb + 18432);  // alias (after QK)
    __nv_bfloat16* plo = (__nv_bfloat16*)(smb + 27648);  // alias (after QK)
    __nv_bfloat16* vth = (__nv_bfloat16*)(smb + 38912);
    __nv_bfloat16* vtl = (__nv_bfloat16*)(smb + 43520);

    const int bh = blockIdx.x;
    const int b  = bh >> 3;
    const int h  = bh & 7;
    const int tid  = threadIdx.x;
    const int lane = tid & 31;
    const int warp = tid >> 5;       // 0..3
    const int g  = lane >> 2, tg = lane & 3;
    const int m0 = warp * 16;
    const int r0 = m0 + g, r1 = r0 + 8;

    // Phase 0: stage q,k fp32; v -> transposed bf16 hi/lo
    const size_t base = (size_t)bh * WIN * HD;
    #pragma unroll
    for (int i = 0; i < 4; i++) {
        const int idx = tid + 128 * i;            // 0..511
        const int n = idx >> 3, c = (idx & 7) * 4;
        *(float4*)&qs[n * 36 + c]  = *(const float4*)&g_q[base + n * HD + c];
        *(float4*)&ksf[n * 36 + c] = *(const float4*)&g_k[base + n * HD + c];
        float4 v = *(const float4*)&g_v[base + n * HD + c];
        float vv[4] = {v.x, v.y, v.z, v.w};
        #pragma unroll
        for (int j = 0; j < 4; j++) {
            const float hf = bf16hi(vv[j]);
            vth[(c + j) * VTP + n] = __float2bfloat16_rn(hf);
            vtl[(c + j) * VTP + n] = __float2bfloat16_rn(vv[j] - hf);
        }
    }
    __syncthreads();

    // Phase 1: row norm (q with logit scale) + bf16 hi/lo split
    {
        const float ls = __expf(fminf(logit_scale[h], 4.6051701859880914f));
        const int row = tid & 63;
        const float* src = (tid < 64) ? &qs[row * 36] : &ksf[row * 36];
        __nv_bfloat16* dhi = (tid < 64) ? &qhi[row * QP] : &khi[row * QP];
        __nv_bfloat16* dlo = (tid < 64) ? &qlo[row * QP] : &klo[row * QP];
        float s = 0.f;
        #pragma unroll
        for (int d = 0; d < HD; d++) s += src[d] * src[d];
        float inv = 1.0f / fmaxf(sqrtf(s), 1e-12f);
        if (tid < 64) inv *= ls;
        #pragma unroll
        for (int d = 0; d < HD; d += 2) {
            const float x0 = src[d] * inv,     x1 = src[d + 1] * inv;
            const float h0 = bf16hi(x0),       h1 = bf16hi(x1);
            *(uint32_t*)&dhi[d] = pack_bf16(h0, h1);
            *(uint32_t*)&dlo[d] = pack_bf16(x0 - h0, x1 - h1);
        }
    }
    __syncthreads();

    // Phase 2: QK^T, 3-term bf16. warp -> rows [m0,m0+16), all 64 cols.
    float acc[8][4] = {};
    #pragma unroll
    for (int kst = 0; kst < 2; kst++) {
        const int kb = kst * 16;
        unsigned ah[4], al[4];
        ah[0] = *(uint32_t*)&qhi[(m0 + g)     * QP + kb + 2 * tg];
        ah[1] = *(uint32_t*)&qhi[(m0 + g + 8) * QP + kb + 2 * tg];
        ah[2] = *(uint32_t*)&qhi[(m0 + g)     * QP + kb + 2 * tg + 8];
        ah[3] = *(uint32_t*)&qhi[(m0 + g + 8) * QP + kb + 2 * tg + 8];
        al[0] = *(uint32_t*)&qlo[(m0 + g)     * QP + kb + 2 * tg];
        al[1] = *(uint32_t*)&qlo[(m0 + g + 8) * QP + kb + 2 * tg];
        al[2] = *(uint32_t*)&qlo[(m0 + g)     * QP + kb + 2 * tg + 8];
        al[3] = *(uint32_t*)&qlo[(m0 + g + 8) * QP + kb + 2 * tg + 8];
        #pragma unroll
        for (int an = 0; an < 8; an++) {
            const int nr = an * 8;
            unsigned bh0 = *(uint32_t*)&khi[(nr + g) * QP + kb + 2 * tg];
            unsigned bh1 = *(uint32_t*)&khi[(nr + g) * QP + kb + 2 * tg + 8];
            unsigned bl0 = *(uint32_t*)&klo[(nr + g) * QP + kb + 2 * tg];
            unsigned bl1 = *(uint32_t*)&klo[(nr + g) * QP + kb + 2 * tg + 8];
            mma_bf16(acc[an], ah[0], ah[1], ah[2], ah[3], bh0, bh1);
            mma_bf16(acc[an], ah[0], ah[1], ah[2], ah[3], bl0, bl1);
            mma_bf16(acc[an], al[0], al[1], al[2], al[3], bh0, bh1);
        }
    }

    // Add bias+mask from L2-resident table
    {
        const float* bm = g_bm + ((size_t)((b & 255) * 8 + h) << 12);
        #pragma unroll
        for (int an = 0; an < 8; an++) {
            const int c = an * 8 + 2 * tg;
            float2 b0 = *(const float2*)&bm[r0 * 64 + c];
            float2 b1 = *(const float2*)&bm[r1 * 64 + c];
            acc[an][0] += b0.x; acc[an][1] += b0.y;
            acc[an][2] += b1.x; acc[an][3] += b1.y;
        }
    }

    // Store logits fp32 (at aliases qs/ks; norm-phase reads finished at last sync)
    #pragma unroll
    for (int an = 0; an < 8; an++) {
        const int c = an * 8 + 2 * tg;
        *(float2*)&at[r0 * ATP + c] = make_float2(acc[an][0], acc[an][1]);
        *(float2*)&at[r1 * ATP + c] = make_float2(acc[an][2], acc[an][3]);
    }
    __syncthreads();

    // Phase 3: softmax (warp per row), write P hi/lo bf16 packed
    for (int i = warp; i < WIN; i += 4) {
        float2 a = *(const float2*)&at[i * ATP + 2 * lane];
        float m = fmaxf(a.x, a.y);
        #pragma unroll
        for (int o = 16; o; o >>= 1) m = fmaxf(m, __shfl_xor_sync(0xffffffffu, m, o));
        float e0 = __expf(a.x - m), e1 = __expf(a.y - m);
        float s = e0 + e1;
        #pragma unroll
        for (int o = 16; o; o >>= 1) s += __shfl_xor_sync(0xffffffffu, s, o);
        const float rinv = 1.0f / s;
        e0 *= rinv; e1 *= rinv;
        const float h0 = bf16hi(e0), h1 = bf16hi(e1);
        *(uint32_t*)&phi[i * PPB + 2 * lane] = pack_bf16(h0, h1);
        *(uint32_t*)&plo[i * PPB + 2 * lane] = pack_bf16(e0 - h0, e1 - h1);
    }
    __syncthreads();

    // Phase 4: out = P @ V, 3-term bf16. warp -> rows [m0,+16), 32 d-cols.
    float oacc[4][4] = {};
    #pragma unroll
    for (int kst = 0; kst < 4; kst++) {
        const int kb = kst * 16;
        unsigned ah[4], al[4];
        ah[0] = *(uint32_t*)&phi[(m0 + g)     * PPB + kb + 2 * tg];
        ah[1] = *(uint32_t*)&phi[(m0 + g + 8) * PPB + kb + 2 * tg];
        ah[2] = *(uint32_t*)&phi[(m0 + g)     * PPB + kb + 2 * tg + 8];
        ah[3] = *(uint32_t*)&phi[(m0 + g + 8) * PPB + kb + 2 * tg + 8];
        al[0] = *(uint32_t*)&plo[(m0 + g)     * PPB + kb + 2 * tg];
        al[1] = *(uint32_t*)&plo[(m0 + g + 8) * PPB + kb + 2 * tg];
        al[2] = *(uint32_t*)&plo[(m0 + g)     * PPB + kb + 2 * tg + 8];
        al[3] = *(uint32_t*)&plo[(m0 + g + 8) * PPB + kb + 2 * tg + 8];
        #pragma unroll
        for (int dn = 0; dn < 4; dn++) {
            const int nn = dn * 8;
            unsigned bh0 = *(uint32_t*)&vth[(nn + g) * VTP + kb + 2 * tg];
            unsigned bh1 = *(uint32_t*)&vth[(nn + g) * VTP + kb + 2 * tg + 8];
            unsigned bl0 = *(uint32_t*)&vtl[(nn + g) * VTP + kb + 2 * tg];
            unsigned bl1 = *(uint32_t*)&vtl[(nn + g) * VTP + kb + 2 * tg + 8];
            mma_bf16(oacc[dn], ah[0], ah[1], ah[2], ah[3], bh0, bh1);
            mma_bf16(oacc[dn], ah[0], ah[1], ah[2], ah[3], bl0, bl1);
            mma_bf16(oacc[dn], al[0], al[1], al[2], al[3], bh0, bh1);
        }
    }

    float* aop = g_ao + (size_t)b * WIN * DIM + h * HD;
    #pragma unroll
    for (int dn = 0; dn < 4; dn++) {
        const int c = dn * 8 + 2 * tg;
        *(float2*)&aop[(size_t)r0 * DIM + c] = make_float2(oacc[dn][0], oacc[dn][1]);
        *(float2*)&aop[(size_t)r1 * DIM + c] = make_float2(oacc[dn][2], oacc[dn][3]);
    }
}

// ---------------------------------------------------------------------------
extern "C" void kernel_launch(void* const* d_in, const int* in_sizes, int n_in,
                              void* d_out, int out_size)
{
    const float* x        = (const float*)d_in[0];
    const float* mask     = (const float*)d_in[1];
    const float* qkv_w    = (const float*)d_in[2];
    const float* qkv_b    = (const float*)d_in[3];
    const float* proj_w   = (const float*)d_in[4];
    const float* proj_b   = (const float*)d_in[5];
    const float* lscale   = (const float*)d_in[6];
    const float* btable   = (const float*)d_in[7];
    const int*   rpi      = (const int*)d_in[8];
    float* out = (float*)d_out;

    cudaFuncSetAttribute(attn_kernel, cudaFuncAttributeMaxDynamicSharedMemorySize,
                         ATTN_SMEM_BYTES);

    // 0) bias+mask tables
    bm_pre<<<32768, 256>>>(btable, rpi, mask);
    // 1) QKV projection
    {
        dim3 grid(QKV_N / 128, MROWS / 128);
        mma_gemm<true><<<grid, 128>>>(x, qkv_w, qkv_b, nullptr);
    }
    // 2) Attention per (window, head)
    {
        attn_kernel<<<NWIN * HEADS, 128, ATTN_SMEM_BYTES>>>(lscale);
    }
    // 3) Output projection
    {
        float* ao = nullptr;
        cudaGetSymbolAddress((void**)&ao, g_ao);
        dim3 grid(DIM / 128, MROWS / 128);
        mma_gemm<false><<<grid, 128>>>(ao, proj_w, proj_b, out);
    }
}